// round 12
// baseline (speedup 1.0000x reference)
#include <cuda_runtime.h>
#include <cuda_bf16.h>
#include <math.h>
#include <stdint.h>

#define NX 8192
#define NY 16384
#define KD 512
#define TOPK 16
#define CAND 24
#define CSTR 25

#define BM 64
#define BN 256
#define BK 32
#define THREADS 256
#define NSTAGES 1024            // (NY/BN=64) * (KD/BK=16)

#define NEG_INF __int_as_float(0xff800000)
#define EXP_LO   -87.3365478515625f
#define FLT_MIN_F 1.17549435082228751e-38f

// ---- smem byte layout ----
#define OFF_XS_B   0                       // bf16 Xs [64][520]        = 66,560
#define OFF_YS_B   66560                   // bf16 Ys [4][256][40]     = 81,920
#define OFF_SIM_B  148480                  // bf16 sim [64][264]       = 33,792 (reused fp32 rv)
#define OFF_CV_B   182272                  // fp32 cv [CAND][64]       =  6,144
#define OFF_CI_B   188416                  // int  ci [CAND][64]       =  6,144
#define SMEM_BYTES 194560

#define XS_RSTRIDE_B 1040    // bytes per Xs row (520 halves)
#define YS_RSTRIDE_B 80      // bytes per Ys row (40 halves: 32 data + pad)
#define YS_STAGE_B   20480   // 256 * 80
#define SIM_WSTRIDE  132     // words per sim row (264 halves)
#define SIM_HSTRIDE  264

__device__ __nv_bfloat16 g_Xbf[(size_t)NX * KD];
__device__ __nv_bfloat16 g_Ybf[(size_t)NY * KD];

__global__ __launch_bounds__(256)
void cvt_kernel(const float* __restrict__ X, const float* __restrict__ Y)
{
    const size_t NXF4 = (size_t)NX * KD / 4;
    const size_t NYF4 = (size_t)NY * KD / 4;
    size_t i = (size_t)blockIdx.x * blockDim.x + threadIdx.x;
    if (i < NXF4) {
        float4 v = ((const float4*)X)[i];
        __nv_bfloat162 lo = __floats2bfloat162_rn(v.x, v.y);
        __nv_bfloat162 hi = __floats2bfloat162_rn(v.z, v.w);
        uint2 u = make_uint2(*(uint32_t*)&lo, *(uint32_t*)&hi);
        *(uint2*)&g_Xbf[i * 4] = u;
    } else if (i < NXF4 + NYF4) {
        size_t j = i - NXF4;
        float4 v = ((const float4*)Y)[j];
        __nv_bfloat162 lo = __floats2bfloat162_rn(v.x, v.y);
        __nv_bfloat162 hi = __floats2bfloat162_rn(v.z, v.w);
        uint2 u = make_uint2(*(uint32_t*)&lo, *(uint32_t*)&hi);
        *(uint2*)&g_Ybf[j * 4] = u;
    }
}

__device__ __forceinline__ uint32_t smem_u32(const void* p) {
    uint32_t a;
    asm("{ .reg .u64 t; cvta.to.shared.u64 t, %1; cvt.u32.u64 %0, t; }" : "=r"(a) : "l"(p));
    return a;
}
__device__ __forceinline__ void cp16(uint32_t dst, const void* src) {
    asm volatile("cp.async.cg.shared.global [%0], [%1], 16;\n" :: "r"(dst), "l"(src) : "memory");
}
__device__ __forceinline__ void ldsm_x4(uint32_t& r0, uint32_t& r1, uint32_t& r2, uint32_t& r3,
                                        uint32_t addr)
{
    asm volatile("ldmatrix.sync.aligned.m8n8.x4.shared.b16 {%0,%1,%2,%3}, [%4];"
                 : "=r"(r0), "=r"(r1), "=r"(r2), "=r"(r3) : "r"(addr));
}
__device__ __forceinline__ void hmma(float c[4], uint32_t a0, uint32_t a1, uint32_t a2, uint32_t a3,
                                     uint32_t b0, uint32_t b1)
{
    asm volatile(
        "mma.sync.aligned.m16n8k16.row.col.f32.bf16.bf16.f32 "
        "{%0,%1,%2,%3}, {%4,%5,%6,%7}, {%8,%9}, {%0,%1,%2,%3};"
        : "+f"(c[0]), "+f"(c[1]), "+f"(c[2]), "+f"(c[3])
        : "r"(a0), "r"(a1), "r"(a2), "r"(a3), "r"(b0), "r"(b1));
}

__global__ __launch_bounds__(THREADS, 1)
void snf_kernel(const float* __restrict__ X, const float* __restrict__ Y,
                float* __restrict__ out)
{
    extern __shared__ __align__(16) char smem[];
    uint32_t*       simW = (uint32_t*)(smem + OFF_SIM_B);
    __nv_bfloat16*  simH = (__nv_bfloat16*)(smem + OFF_SIM_B);
    float*          rv   = (float*)(smem + OFF_SIM_B);
    float*          cv   = (float*)(smem + OFF_CV_B);
    int*            ci   = (int*)(smem + OFF_CI_B);

    const int tid  = threadIdx.x;
    const int warp = tid >> 5;
    const int lane = tid & 31;
    const int g    = lane >> 2;
    const int t    = lane & 3;
    const int mw   = warp & 1;     // m group (32 rows)
    const int nw   = warp >> 1;    // n group (64 cols)
    const int row0 = blockIdx.x * BM;
    const uint32_t sbase = smem_u32(smem);

    // hoisted LDSM lane addresses
    // A x4 (m16 x k16): lanes 0-15 rows, 16-31 same rows @k8 (+16B)
    const uint32_t aLane = sbase + OFF_XS_B
        + (uint32_t)(mw * 32 + (lane & 15)) * XS_RSTRIDE_B + ((lane >> 4) << 4);
    // B x4 (n16 x k16 = two n8 tiles): 0-7 n lo @k0, 8-15 n lo @k8, 16-23 n hi @k0, 24-31 n hi @k8
    const uint32_t bLane = (uint32_t)(nw * 64 + ((lane >> 4) & 1) * 8 + (lane & 7)) * YS_RSTRIDE_B
        + (((lane >> 3) & 1) << 4);

    // ---- prologue: issue cp.async stages 0..2 ----
    #pragma unroll
    for (int ps = 0; ps < 3; ps++) {
        int kt1 = ps * BK;             // jt=0 for ps<16
        #pragma unroll
        for (int s2 = 0; s2 < 4; s2++) {
            int ch = tid + s2 * THREADS;   // 0..1023
            int n = ch >> 2, c = ch & 3;
            cp16(sbase + OFF_YS_B + ps * YS_STAGE_B + n * YS_RSTRIDE_B + c * 16,
                 g_Ybf + (size_t)n * KD + kt1 + c * 8);
        }
        asm volatile("cp.async.commit_group;" ::: "memory");
    }

    // ---- fill bf16 Xs tile ----
    {
        const uint4* xsrc = (const uint4*)(g_Xbf + (size_t)row0 * KD);
        #pragma unroll
        for (int i = 0; i < 16; i++) {
            int f = tid + i * THREADS;   // 0..4095
            int m = f >> 6, c = f & 63;
            *(uint4*)(smem + OFF_XS_B + m * XS_RSTRIDE_B + c * 16) = xsrc[m * 64 + c];
        }
    }
    for (int i = tid; i < CAND * BM; i += THREADS) { cv[i] = NEG_INF; ci[i] = 0; }

    float acc[2][8][4];   // [mt][nt8][quad] = 64 regs

    for (int S = 0; S < NSTAGES; S++) {
        asm volatile("cp.async.wait_group 2;" ::: "memory");
        __syncthreads();

        // issue stage S+3 into buffer (S+3)&3 (old contents consumed at S-1)
        if (S + 3 < NSTAGES) {
            int ps = S + 3;
            int jt1 = ps >> 4, kt1 = (ps & 15) * BK;
            uint32_t dstb = sbase + OFF_YS_B + (ps & 3) * YS_STAGE_B;
            const __nv_bfloat16* srcb = g_Ybf + (size_t)jt1 * BN * KD + kt1;
            #pragma unroll
            for (int s2 = 0; s2 < 4; s2++) {
                int ch = tid + s2 * THREADS;
                int n = ch >> 2, c = ch & 3;
                cp16(dstb + n * YS_RSTRIDE_B + c * 16, srcb + (size_t)n * KD + c * 8);
            }
        }
        asm volatile("cp.async.commit_group;" ::: "memory");

        // ---- compute stage S ----
        const uint32_t aStage = aLane + (uint32_t)(S & 15) * (BK * 2);  // 64 B per stage
        const uint32_t bStage = sbase + OFF_YS_B + (S & 3) * YS_STAGE_B + bLane;

        if ((S & 15) == 0) {
            #pragma unroll
            for (int mt = 0; mt < 2; mt++)
                #pragma unroll
                for (int nt = 0; nt < 8; nt++)
                    #pragma unroll
                    for (int q = 0; q < 4; q++) acc[mt][nt][q] = 0.0f;
        }

        #pragma unroll
        for (int ks = 0; ks < 2; ks++) {
            uint32_t a0[4], a1[4];
            ldsm_x4(a0[0], a0[1], a0[2], a0[3], aStage + ks * 32);
            ldsm_x4(a1[0], a1[1], a1[2], a1[3], aStage + 16 * XS_RSTRIDE_B + ks * 32);
            uint32_t b[16];
            #pragma unroll
            for (int nn = 0; nn < 4; nn++)
                ldsm_x4(b[nn * 4 + 0], b[nn * 4 + 1], b[nn * 4 + 2], b[nn * 4 + 3],
                        bStage + nn * (16 * YS_RSTRIDE_B) + ks * 32);
            #pragma unroll
            for (int nt = 0; nt < 8; nt++) {
                hmma(acc[0][nt], a0[0], a0[1], a0[2], a0[3], b[nt * 2], b[nt * 2 + 1]);
                hmma(acc[1][nt], a1[0], a1[1], a1[2], a1[3], b[nt * 2], b[nt * 2 + 1]);
            }
        }

        if ((S & 15) == 15) {
            const int jt = (S >> 4) * BN;
            // dump approx sims as bf16 pairs
            #pragma unroll
            for (int mt = 0; mt < 2; mt++)
                #pragma unroll
                for (int nt = 0; nt < 8; nt++) {
                    int r0 = mw * 32 + mt * 16 + g;
                    int cw = nw * 32 + nt * 4 + t;   // word column
                    __nv_bfloat162 p0 = __floats2bfloat162_rn(acc[mt][nt][0], acc[mt][nt][1]);
                    __nv_bfloat162 p1 = __floats2bfloat162_rn(acc[mt][nt][2], acc[mt][nt][3]);
                    simW[(r0 + 0) * SIM_WSTRIDE + cw] = *(uint32_t*)&p0;
                    simW[(r0 + 8) * SIM_WSTRIDE + cw] = *(uint32_t*)&p1;
                }
            __syncthreads();

            // candidate scan: warp w owns rows 8w..8w+7, 8 cols per lane
            #pragma unroll
            for (int rr = 0; rr < 8; rr++) {
                const int r = warp * 8 + rr;
                float v[8]; int jj[8];
                #pragma unroll
                for (int c = 0; c < 8; c++) {
                    v[c]  = __bfloat162float(simH[r * SIM_HSTRIDE + lane + c * 32]);
                    jj[c] = jt + lane + c * 32;
                }
                while (true) {
                    float thr = cv[(CAND - 1) * BM + r];
                    bool any = false;
                    #pragma unroll
                    for (int c = 0; c < 8; c++) any |= (v[c] > thr);
                    if (!__ballot_sync(0xffffffffu, any)) break;
                    float bmv = NEG_INF; int bj = 0x7fffffff;
                    #pragma unroll
                    for (int c = 0; c < 8; c++)
                        if (v[c] > thr && (v[c] > bmv || (v[c] == bmv && jj[c] < bj))) {
                            bmv = v[c]; bj = jj[c];
                        }
                    #pragma unroll
                    for (int off = 16; off > 0; off >>= 1) {
                        float ov = __shfl_xor_sync(0xffffffffu, bmv, off);
                        int   oj = __shfl_xor_sync(0xffffffffu, bj,  off);
                        if (ov > bmv || (ov == bmv && oj < bj)) { bmv = ov; bj = oj; }
                    }
                    if (lane == 0) {
                        int p = CAND - 1;
                        while (p > 0 && bmv > cv[(p - 1) * BM + r]) {
                            cv[p * BM + r] = cv[(p - 1) * BM + r];
                            ci[p * BM + r] = ci[(p - 1) * BM + r];
                            p--;
                        }
                        cv[p * BM + r] = bmv; ci[p * BM + r] = bj;
                    }
                    __syncwarp();
                    #pragma unroll
                    for (int c = 0; c < 8; c++)
                        if (v[c] == bmv && jj[c] == bj) v[c] = NEG_INF;
                }
            }
        }
    }
    __syncthreads();

    // ---- EXACT rescore: sequential-k fp32 fmaf chain (bit-identical to ref) ----
    {
        float acc6[6];
        int   mloc[6], cloc[6];
        const float4* xp[6];
        const float4* yp[6];
        #pragma unroll
        for (int d = 0; d < 6; d++) {
            int idx = tid + d * THREADS;        // 0..1535 = CAND*BM-1
            int m = idx / CAND, c = idx % CAND;
            mloc[d] = m; cloc[d] = c;
            xp[d] = (const float4*)(X + (size_t)(row0 + m) * KD);
            yp[d] = (const float4*)(Y + (size_t)ci[c * BM + m] * KD);
            acc6[d] = 0.0f;
        }
        for (int k4 = 0; k4 < KD / 4; k4++) {
            #pragma unroll
            for (int d = 0; d < 6; d++) {
                float4 x4 = __ldg(xp[d] + k4);
                float4 y4 = __ldg(yp[d] + k4);
                float a = acc6[d];
                a = fmaf(x4.x, y4.x, a);
                a = fmaf(x4.y, y4.y, a);
                a = fmaf(x4.z, y4.z, a);
                a = fmaf(x4.w, y4.w, a);
                acc6[d] = a;
            }
        }
        __syncthreads();   // scan reads of sim done; area becomes rv
        #pragma unroll
        for (int d = 0; d < 6; d++)
            rv[mloc[d] * CSTR + cloc[d]] = __fdiv_rn(acc6[d], 0.07f);
    }
    __syncthreads();

    // ---- exact FTZ-softmax epilogue (unchanged passing rule) ----
    if (tid < BM) {
        const int r = tid;
        float pv[CAND]; int id[CAND];
        #pragma unroll
        for (int c = 0; c < CAND; c++) { pv[c] = rv[r * CSTR + c]; id[c] = ci[c * BM + r]; }

        for (int i = 1; i < CAND; i++) {
            float kp = pv[i]; int kd = id[i];
            int j2 = i - 1;
            while (j2 >= 0 && (pv[j2] < kp || (pv[j2] == kp && id[j2] > kd))) {
                pv[j2 + 1] = pv[j2]; id[j2 + 1] = id[j2];
                j2--;
            }
            pv[j2 + 1] = kp; id[j2 + 1] = kd;
        }

        const float M = pv[0];
        float ef[CAND]; float S = 0.0f;
        #pragma unroll
        for (int c = 0; c < CAND; c++) {
            float d = pv[c] - M;
            float e = 0.0f;
            if (d > EXP_LO) {
                e = __double2float_rn(exp((double)d));
                if (e < FLT_MIN_F) e = 0.0f;
            }
            ef[c] = e;
            S += e;
        }

        int outv[TOPK]; int cnt = 0;
        for (int c = 0; c < CAND && cnt < TOPK; c++) {
            if (ef[c] > 0.0f) {
                float q = __fdiv_rn(ef[c], S);
                if (q >= FLT_MIN_F) outv[cnt++] = id[c];
            }
        }
        const int nz = cnt;
        for (int j = 0; cnt < TOPK; j++) {
            bool used = false;
            for (int q2 = 0; q2 < nz; q2++)
                if (outv[q2] == j) { used = true; break; }
            if (!used) outv[cnt++] = j;
        }

        #pragma unroll
        for (int k = 0; k < TOPK; k++)
            out[(size_t)(row0 + r) * TOPK + k] = (float)outv[k];
    }
}

extern "C" void kernel_launch(void* const* d_in, const int* in_sizes, int n_in,
                              void* d_out, int out_size)
{
    const float* X = (const float*)d_in[0];
    const float* Y = (const float*)d_in[1];
    if (n_in >= 2 && in_sizes[0] == NY * KD && in_sizes[1] == NX * KD) {
        X = (const float*)d_in[1];
        Y = (const float*)d_in[0];
    }
    float* out = (float*)d_out;
    (void)out_size;

    static int attr_set = 0;
    if (!attr_set) {
        cudaFuncSetAttribute(snf_kernel, cudaFuncAttributeMaxDynamicSharedMemorySize,
                             SMEM_BYTES);
        attr_set = 1;
    }

    const int cvt_blocks = (NX * KD / 4 + NY * KD / 4 + 255) / 256;
    cvt_kernel<<<cvt_blocks, 256>>>(X, Y);
    snf_kernel<<<NX / BM, THREADS, SMEM_BYTES>>>(X, Y, out);
}

// round 13
// speedup vs baseline: 1.5647x; 1.5647x over previous
#include <cuda_runtime.h>
#include <cuda_bf16.h>
#include <math.h>
#include <stdint.h>

#define NX 8192
#define NY 16384
#define KD 512
#define TOPK 16
#define CAND 24
#define CSTR 25

#define BM 32
#define BN 128
#define BK 64
#define THREADS 256
#define NSTAGES 1024            // (NY/BN=128) * (KD/BK=8)

#define NEG_INF __int_as_float(0xff800000)
#define EXP_LO   -87.3365478515625f
#define FLT_MIN_F 1.17549435082228751e-38f

// ---- smem byte layout (per CTA: 103,424 B -> 2 CTAs/SM) ----
#define OFF_XS_B   0                       // bf16 Xs [32][520]        = 33,280
#define OFF_YS_B   33280                   // bf16 Ys [3][128][72]     = 55,296
#define OFF_SIM_B  88576                   // bf16 sim [32][136]       =  8,704 (reused fp32 rv)
#define OFF_CV_B   97280                   // fp32 cv [CAND][32]       =  3,072
#define OFF_CI_B   100352                  // int  ci [CAND][32]       =  3,072
#define SMEM_BYTES 103424

#define XS_RSTRIDE_B 1040    // bytes per Xs row (520 halves)
#define YS_RSTRIDE_B 144     // bytes per Ys row (72 halves: 64 data + 8 pad)
#define YS_STAGE_B   18432   // 128 * 144
#define SIM_WSTRIDE  68
#define SIM_HSTRIDE  136

__device__ __nv_bfloat16 g_Xbf[(size_t)NX * KD];
__device__ __nv_bfloat16 g_Ybf[(size_t)NY * KD];

__global__ __launch_bounds__(256)
void cvt_kernel(const float* __restrict__ X, const float* __restrict__ Y)
{
    const size_t NXF4 = (size_t)NX * KD / 4;
    const size_t NYF4 = (size_t)NY * KD / 4;
    size_t i = (size_t)blockIdx.x * blockDim.x + threadIdx.x;
    if (i < NXF4) {
        float4 v = ((const float4*)X)[i];
        __nv_bfloat162 lo = __floats2bfloat162_rn(v.x, v.y);
        __nv_bfloat162 hi = __floats2bfloat162_rn(v.z, v.w);
        uint2 u = make_uint2(*(uint32_t*)&lo, *(uint32_t*)&hi);
        *(uint2*)&g_Xbf[i * 4] = u;
    } else if (i < NXF4 + NYF4) {
        size_t j = i - NXF4;
        float4 v = ((const float4*)Y)[j];
        __nv_bfloat162 lo = __floats2bfloat162_rn(v.x, v.y);
        __nv_bfloat162 hi = __floats2bfloat162_rn(v.z, v.w);
        uint2 u = make_uint2(*(uint32_t*)&lo, *(uint32_t*)&hi);
        *(uint2*)&g_Ybf[j * 4] = u;
    }
}

__device__ __forceinline__ uint32_t smem_u32(const void* p) {
    uint32_t a;
    asm("{ .reg .u64 t; cvta.to.shared.u64 t, %1; cvt.u32.u64 %0, t; }" : "=r"(a) : "l"(p));
    return a;
}
__device__ __forceinline__ void cp16(uint32_t dst, const void* src) {
    asm volatile("cp.async.cg.shared.global [%0], [%1], 16;\n" :: "r"(dst), "l"(src) : "memory");
}
__device__ __forceinline__ void ldsm_x4(uint32_t& r0, uint32_t& r1, uint32_t& r2, uint32_t& r3,
                                        uint32_t addr)
{
    asm volatile("ldmatrix.sync.aligned.m8n8.x4.shared.b16 {%0,%1,%2,%3}, [%4];"
                 : "=r"(r0), "=r"(r1), "=r"(r2), "=r"(r3) : "r"(addr));
}
__device__ __forceinline__ void hmma(float c[4], const uint32_t a[4],
                                     uint32_t b0, uint32_t b1)
{
    asm volatile(
        "mma.sync.aligned.m16n8k16.row.col.f32.bf16.bf16.f32 "
        "{%0,%1,%2,%3}, {%4,%5,%6,%7}, {%8,%9}, {%0,%1,%2,%3};"
        : "+f"(c[0]), "+f"(c[1]), "+f"(c[2]), "+f"(c[3])
        : "r"(a[0]), "r"(a[1]), "r"(a[2]), "r"(a[3]), "r"(b0), "r"(b1));
}

__global__ __launch_bounds__(THREADS, 2)
void snf_kernel(const float* __restrict__ X, const float* __restrict__ Y,
                float* __restrict__ out)
{
    extern __shared__ __align__(16) char smem[];
    uint32_t*       simW = (uint32_t*)(smem + OFF_SIM_B);
    __nv_bfloat16*  simH = (__nv_bfloat16*)(smem + OFF_SIM_B);
    float*          rv   = (float*)(smem + OFF_SIM_B);
    float*          cv   = (float*)(smem + OFF_CV_B);
    int*            ci   = (int*)(smem + OFF_CI_B);

    const int tid  = threadIdx.x;
    const int warp = tid >> 5;
    const int lane = tid & 31;
    const int g    = lane >> 2;
    const int t    = lane & 3;
    const int mw   = warp & 1;     // m group (16 rows)
    const int nw   = warp >> 1;    // n group (32 cols)
    const int row0 = blockIdx.x * BM;
    const uint32_t sbase = smem_u32(smem);

    // hoisted LDSM lane addresses
    // A x4 (m16 x k16): lanes 0-15 rows, 16-31 same rows @k8 (+16B)
    const uint32_t aLane = sbase + OFF_XS_B
        + (uint32_t)(mw * 16 + (lane & 15)) * XS_RSTRIDE_B + ((lane >> 4) << 4);
    // B x4 (two n8 tiles): 0-7 n lo @k0, 8-15 n lo @k8, 16-23 n hi @k0, 24-31 n hi @k8
    const uint32_t bLane = (uint32_t)(nw * 32 + ((lane >> 4) & 1) * 8 + (lane & 7)) * YS_RSTRIDE_B
        + (((lane >> 3) & 1) << 4);

    // ---- prologue: issue cp.async stages 0,1 ----
    #pragma unroll
    for (int ps = 0; ps < 2; ps++) {
        int kt1 = ps * BK;            // jt=0 for ps<8
        #pragma unroll
        for (int s2 = 0; s2 < 4; s2++) {
            int ch = tid + s2 * THREADS;   // 0..1023
            int n = ch >> 3, c = ch & 7;
            cp16(sbase + OFF_YS_B + ps * YS_STAGE_B + n * YS_RSTRIDE_B + c * 16,
                 g_Ybf + (size_t)n * KD + kt1 + c * 8);
        }
        asm volatile("cp.async.commit_group;" ::: "memory");
    }

    // ---- fill bf16 Xs tile ----
    {
        const uint4* xsrc = (const uint4*)(g_Xbf + (size_t)row0 * KD);
        #pragma unroll
        for (int i = 0; i < 8; i++) {
            int f = tid + i * THREADS;   // 0..2047
            int m = f >> 6, c = f & 63;
            *(uint4*)(smem + OFF_XS_B + m * XS_RSTRIDE_B + c * 16) = xsrc[m * 64 + c];
        }
    }
    for (int i = tid; i < CAND * BM; i += THREADS) { cv[i] = NEG_INF; ci[i] = 0; }

    float acc[4][4];   // [nt][quad] = 16 regs
    int cbuf = 0, ibuf = 2;

    for (int S = 0; S < NSTAGES; S++) {
        asm volatile("cp.async.wait_group 1;" ::: "memory");
        __syncthreads();

        // issue stage S+2 into buffer ibuf (old contents consumed at stage S-1)
        if (S + 2 < NSTAGES) {
            int ps = S + 2;
            int jt1 = ps >> 3, kt1 = (ps & 7) * BK;
            uint32_t dstb = sbase + OFF_YS_B + ibuf * YS_STAGE_B;
            const __nv_bfloat16* srcb = g_Ybf + (size_t)jt1 * BN * KD + kt1;
            #pragma unroll
            for (int s2 = 0; s2 < 4; s2++) {
                int ch = tid + s2 * THREADS;
                int n = ch >> 3, c = ch & 7;
                cp16(dstb + n * YS_RSTRIDE_B + c * 16, srcb + (size_t)n * KD + c * 8);
            }
        }
        asm volatile("cp.async.commit_group;" ::: "memory");

        // ---- compute stage S from buffer cbuf ----
        const uint32_t aStage = aLane + (uint32_t)(S & 7) * (BK * 2);  // 128 B per stage
        const uint32_t bStage = sbase + OFF_YS_B + cbuf * YS_STAGE_B + bLane;

        if ((S & 7) == 0) {
            #pragma unroll
            for (int nt = 0; nt < 4; nt++)
                #pragma unroll
                for (int q = 0; q < 4; q++) acc[nt][q] = 0.0f;
        }

        #pragma unroll
        for (int ks = 0; ks < 4; ks++) {
            uint32_t a[4];
            ldsm_x4(a[0], a[1], a[2], a[3], aStage + ks * 32);
            uint32_t b0, b1, b2, b3, b4, b5, b6, b7;
            ldsm_x4(b0, b1, b2, b3, bStage + ks * 32);                     // nt 0,1
            ldsm_x4(b4, b5, b6, b7, bStage + 16 * YS_RSTRIDE_B + ks * 32); // nt 2,3
            hmma(acc[0], a, b0, b1);
            hmma(acc[1], a, b2, b3);
            hmma(acc[2], a, b4, b5);
            hmma(acc[3], a, b6, b7);
        }

        if ((S & 7) == 7) {
            const int jt = (S >> 3) * BN;
            // dump approx sims as bf16 pairs
            #pragma unroll
            for (int nt = 0; nt < 4; nt++) {
                int r0 = mw * 16 + g;
                int cw = nw * 16 + nt * 4 + t;
                __nv_bfloat162 p0 = __floats2bfloat162_rn(acc[nt][0], acc[nt][1]);
                __nv_bfloat162 p1 = __floats2bfloat162_rn(acc[nt][2], acc[nt][3]);
                simW[(r0 + 0) * SIM_WSTRIDE + cw] = *(uint32_t*)&p0;
                simW[(r0 + 8) * SIM_WSTRIDE + cw] = *(uint32_t*)&p1;
            }
            __syncthreads();

            // candidate scan: warp w owns rows 4w..4w+3
            #pragma unroll
            for (int rr = 0; rr < 4; rr++) {
                const int r = warp * 4 + rr;
                float v[4]; int jj[4];
                #pragma unroll
                for (int c = 0; c < 4; c++) {
                    v[c]  = __bfloat162float(simH[r * SIM_HSTRIDE + lane + c * 32]);
                    jj[c] = jt + lane + c * 32;
                }
                while (true) {
                    float thr = cv[(CAND - 1) * BM + r];
                    bool any = (v[0] > thr) | (v[1] > thr) | (v[2] > thr) | (v[3] > thr);
                    if (!__ballot_sync(0xffffffffu, any)) break;
                    float bmv = NEG_INF; int bj = 0x7fffffff;
                    #pragma unroll
                    for (int c = 0; c < 4; c++)
                        if (v[c] > thr && (v[c] > bmv || (v[c] == bmv && jj[c] < bj))) {
                            bmv = v[c]; bj = jj[c];
                        }
                    #pragma unroll
                    for (int off = 16; off > 0; off >>= 1) {
                        float ov = __shfl_xor_sync(0xffffffffu, bmv, off);
                        int   oj = __shfl_xor_sync(0xffffffffu, bj,  off);
                        if (ov > bmv || (ov == bmv && oj < bj)) { bmv = ov; bj = oj; }
                    }
                    if (lane == 0) {
                        int p = CAND - 1;
                        while (p > 0 && bmv > cv[(p - 1) * BM + r]) {
                            cv[p * BM + r] = cv[(p - 1) * BM + r];
                            ci[p * BM + r] = ci[(p - 1) * BM + r];
                            p--;
                        }
                        cv[p * BM + r] = bmv; ci[p * BM + r] = bj;
                    }
                    __syncwarp();
                    #pragma unroll
                    for (int c = 0; c < 4; c++)
                        if (v[c] == bmv && jj[c] == bj) v[c] = NEG_INF;
                }
            }
        }

        cbuf = (cbuf == 2) ? 0 : cbuf + 1;
        ibuf = (ibuf == 2) ? 0 : ibuf + 1;
    }
    __syncthreads();

    // ---- EXACT rescore: sequential-k fp32 fmaf chain (bit-identical to ref) ----
    {
        float acc3[3];
        int   mloc[3], cloc[3];
        const float4* xp[3];
        const float4* yp[3];
        #pragma unroll
        for (int d = 0; d < 3; d++) {
            int idx = tid + d * THREADS;        // 0..767 = CAND*BM-1
            int m = idx / CAND, c = idx % CAND;
            mloc[d] = m; cloc[d] = c;
            xp[d] = (const float4*)(X + (size_t)(row0 + m) * KD);
            yp[d] = (const float4*)(Y + (size_t)ci[c * BM + m] * KD);
            acc3[d] = 0.0f;
        }
        for (int k4 = 0; k4 < KD / 4; k4++) {
            #pragma unroll
            for (int d = 0; d < 3; d++) {
                float4 x4 = __ldg(xp[d] + k4);
                float4 y4 = __ldg(yp[d] + k4);
                float a = acc3[d];
                a = fmaf(x4.x, y4.x, a);
                a = fmaf(x4.y, y4.y, a);
                a = fmaf(x4.z, y4.z, a);
                a = fmaf(x4.w, y4.w, a);
                acc3[d] = a;
            }
        }
        __syncthreads();   // scan reads of sim done; area becomes rv
        #pragma unroll
        for (int d = 0; d < 3; d++)
            rv[mloc[d] * CSTR + cloc[d]] = __fdiv_rn(acc3[d], 0.07f);
    }
    __syncthreads();

    // ---- exact FTZ-softmax epilogue (unchanged passing rule) ----
    if (tid < BM) {
        const int r = tid;
        float pv[CAND]; int id[CAND];
        #pragma unroll
        for (int c = 0; c < CAND; c++) { pv[c] = rv[r * CSTR + c]; id[c] = ci[c * BM + r]; }

        for (int i = 1; i < CAND; i++) {
            float kp = pv[i]; int kd = id[i];
            int j2 = i - 1;
            while (j2 >= 0 && (pv[j2] < kp || (pv[j2] == kp && id[j2] > kd))) {
                pv[j2 + 1] = pv[j2]; id[j2 + 1] = id[j2];
                j2--;
            }
            pv[j2 + 1] = kp; id[j2 + 1] = kd;
        }

        const float M = pv[0];
        float ef[CAND]; float S = 0.0f;
        #pragma unroll
        for (int c = 0; c < CAND; c++) {
            float d = pv[c] - M;
            float e = 0.0f;
            if (d > EXP_LO) {
                e = __double2float_rn(exp((double)d));
                if (e < FLT_MIN_F) e = 0.0f;
            }
            ef[c] = e;
            S += e;
        }

        int outv[TOPK]; int cnt = 0;
        for (int c = 0; c < CAND && cnt < TOPK; c++) {
            if (ef[c] > 0.0f) {
                float q = __fdiv_rn(ef[c], S);
                if (q >= FLT_MIN_F) outv[cnt++] = id[c];
            }
        }
        const int nz = cnt;
        for (int j = 0; cnt < TOPK; j++) {
            bool used = false;
            for (int q2 = 0; q2 < nz; q2++)
                if (outv[q2] == j) { used = true; break; }
            if (!used) outv[cnt++] = j;
        }

        #pragma unroll
        for (int k = 0; k < TOPK; k++)
            out[(size_t)(row0 + r) * TOPK + k] = (float)outv[k];
    }
}

extern "C" void kernel_launch(void* const* d_in, const int* in_sizes, int n_in,
                              void* d_out, int out_size)
{
    const float* X = (const float*)d_in[0];
    const float* Y = (const float*)d_in[1];
    if (n_in >= 2 && in_sizes[0] == NY * KD && in_sizes[1] == NX * KD) {
        X = (const float*)d_in[1];
        Y = (const float*)d_in[0];
    }
    float* out = (float*)d_out;
    (void)out_size;

    static int attr_set = 0;
    if (!attr_set) {
        cudaFuncSetAttribute(snf_kernel, cudaFuncAttributeMaxDynamicSharedMemorySize,
                             SMEM_BYTES);
        attr_set = 1;
    }

    const int cvt_blocks = (NX * KD / 4 + NY * KD / 4 + 255) / 256;
    cvt_kernel<<<cvt_blocks, 256>>>(X, Y);
    snf_kernel<<<NX / BM, THREADS, SMEM_BYTES>>>(X, Y, out);
}

// round 14
// speedup vs baseline: 1.7052x; 1.0898x over previous
#include <cuda_runtime.h>
#include <cuda_bf16.h>
#include <math.h>
#include <stdint.h>

#define NX 8192
#define NY 16384
#define KD 512
#define TOPK 16
#define CAND 24
#define CSTR 25

#define BM 64
#define BN 128
#define BK 128
#define THREADS 512
#define NSTAGES 512             // (NY/BN=128) * (KD/BK=4)

#define NEG_INF __int_as_float(0xff800000)
#define EXP_LO   -87.3365478515625f
#define FLT_MIN_F 1.17549435082228751e-38f

// ---- smem byte layout ----
#define OFF_XS_B   0                       // bf16 Xs [64][520]        = 66,560
#define OFF_YS_B   66560                   // bf16 Ys [3][128][136]    = 104,448
#define OFF_SIM_B  171008                  // bf16 sim [64][136]       = 17,408 (reused fp32 rv)
#define OFF_CV_B   188416                  // fp32 cv [CAND][64]       =  6,144
#define OFF_CI_B   194560                  // int  ci [CAND][64]       =  6,144
#define SMEM_BYTES 200704

#define XS_RSTRIDE_B 1040    // bytes per Xs row (520 halves)
#define YS_RSTRIDE_B 272     // bytes per Ys row (136 halves: 128 data + 8 pad)
#define YS_STAGE_B   34816   // 128 * 272
#define SIM_WSTRIDE  68
#define SIM_HSTRIDE  136

__device__ __nv_bfloat16 g_Xbf[(size_t)NX * KD];
__device__ __nv_bfloat16 g_Ybf[(size_t)NY * KD];

__global__ __launch_bounds__(256)
void cvt_kernel(const float* __restrict__ X, const float* __restrict__ Y)
{
    const size_t NXF4 = (size_t)NX * KD / 4;
    const size_t NYF4 = (size_t)NY * KD / 4;
    size_t i = (size_t)blockIdx.x * blockDim.x + threadIdx.x;
    if (i < NXF4) {
        float4 v = ((const float4*)X)[i];
        __nv_bfloat162 lo = __floats2bfloat162_rn(v.x, v.y);
        __nv_bfloat162 hi = __floats2bfloat162_rn(v.z, v.w);
        uint2 u = make_uint2(*(uint32_t*)&lo, *(uint32_t*)&hi);
        *(uint2*)&g_Xbf[i * 4] = u;
    } else if (i < NXF4 + NYF4) {
        size_t j = i - NXF4;
        float4 v = ((const float4*)Y)[j];
        __nv_bfloat162 lo = __floats2bfloat162_rn(v.x, v.y);
        __nv_bfloat162 hi = __floats2bfloat162_rn(v.z, v.w);
        uint2 u = make_uint2(*(uint32_t*)&lo, *(uint32_t*)&hi);
        *(uint2*)&g_Ybf[j * 4] = u;
    }
}

__device__ __forceinline__ uint32_t smem_u32(const void* p) {
    uint32_t a;
    asm("{ .reg .u64 t; cvta.to.shared.u64 t, %1; cvt.u32.u64 %0, t; }" : "=r"(a) : "l"(p));
    return a;
}
__device__ __forceinline__ void cp16(uint32_t dst, const void* src) {
    asm volatile("cp.async.cg.shared.global [%0], [%1], 16;\n" :: "r"(dst), "l"(src) : "memory");
}
__device__ __forceinline__ void ldsm_x4(uint32_t& r0, uint32_t& r1, uint32_t& r2, uint32_t& r3,
                                        uint32_t addr)
{
    asm volatile("ldmatrix.sync.aligned.m8n8.x4.shared.b16 {%0,%1,%2,%3}, [%4];"
                 : "=r"(r0), "=r"(r1), "=r"(r2), "=r"(r3) : "r"(addr));
}
__device__ __forceinline__ void hmma(float c[4], const uint32_t a[4],
                                     uint32_t b0, uint32_t b1)
{
    asm volatile(
        "mma.sync.aligned.m16n8k16.row.col.f32.bf16.bf16.f32 "
        "{%0,%1,%2,%3}, {%4,%5,%6,%7}, {%8,%9}, {%0,%1,%2,%3};"
        : "+f"(c[0]), "+f"(c[1]), "+f"(c[2]), "+f"(c[3])
        : "r"(a[0]), "r"(a[1]), "r"(a[2]), "r"(a[3]), "r"(b0), "r"(b1));
}

__global__ __launch_bounds__(THREADS, 1)
void snf_kernel(const float* __restrict__ X, const float* __restrict__ Y,
                float* __restrict__ out)
{
    extern __shared__ __align__(16) char smem[];
    uint32_t*       simW = (uint32_t*)(smem + OFF_SIM_B);
    __nv_bfloat16*  simH = (__nv_bfloat16*)(smem + OFF_SIM_B);
    float*          rv   = (float*)(smem + OFF_SIM_B);
    float*          cv   = (float*)(smem + OFF_CV_B);
    int*            ci   = (int*)(smem + OFF_CI_B);

    const int tid  = threadIdx.x;
    const int warp = tid >> 5;
    const int lane = tid & 31;
    const int g    = lane >> 2;
    const int t    = lane & 3;
    const int mw   = warp & 3;     // m group (16 rows)
    const int nw   = warp >> 2;    // n group (32 cols)
    const int row0 = blockIdx.x * BM;
    const uint32_t sbase = smem_u32(smem);

    // hoisted LDSM lane addresses
    const uint32_t aLane = sbase + OFF_XS_B
        + (uint32_t)(mw * 16 + (lane & 15)) * XS_RSTRIDE_B + ((lane >> 4) << 4);
    const uint32_t bLane = (uint32_t)(nw * 32 + ((lane >> 4) & 1) * 8 + (lane & 7)) * YS_RSTRIDE_B
        + (((lane >> 3) & 1) << 4);

    // ---- prologue: issue cp.async stages 0,1 ----
    #pragma unroll
    for (int ps = 0; ps < 2; ps++) {
        int kt1 = ps * BK;            // jt=0 for ps<4
        #pragma unroll
        for (int s2 = 0; s2 < 4; s2++) {
            int ch = tid + s2 * THREADS;   // 0..2047
            int n = ch >> 4, c = ch & 15;
            cp16(sbase + OFF_YS_B + ps * YS_STAGE_B + n * YS_RSTRIDE_B + c * 16,
                 g_Ybf + (size_t)n * KD + kt1 + c * 8);
        }
        asm volatile("cp.async.commit_group;" ::: "memory");
    }

    // ---- fill bf16 Xs tile ----
    {
        const uint4* xsrc = (const uint4*)(g_Xbf + (size_t)row0 * KD);
        #pragma unroll
        for (int i = 0; i < 8; i++) {
            int f = tid + i * THREADS;   // 0..4095
            int m = f >> 6, c = f & 63;
            *(uint4*)(smem + OFF_XS_B + m * XS_RSTRIDE_B + c * 16) = xsrc[m * 64 + c];
        }
    }
    for (int i = tid; i < CAND * BM; i += THREADS) { cv[i] = NEG_INF; ci[i] = 0; }

    float acc[4][4];   // [nt][quad] = 16 regs
    int cbuf = 0, ibuf = 2;

    for (int S = 0; S < NSTAGES; S++) {
        asm volatile("cp.async.wait_group 1;" ::: "memory");
        __syncthreads();

        // issue stage S+2 into buffer ibuf (old contents consumed at stage S-1)
        if (S + 2 < NSTAGES) {
            int ps = S + 2;
            int jt1 = ps >> 2, kt1 = (ps & 3) * BK;
            uint32_t dstb = sbase + OFF_YS_B + ibuf * YS_STAGE_B;
            const __nv_bfloat16* srcb = g_Ybf + (size_t)jt1 * BN * KD + kt1;
            #pragma unroll
            for (int s2 = 0; s2 < 4; s2++) {
                int ch = tid + s2 * THREADS;
                int n = ch >> 4, c = ch & 15;
                cp16(dstb + n * YS_RSTRIDE_B + c * 16, srcb + (size_t)n * KD + c * 8);
            }
        }
        asm volatile("cp.async.commit_group;" ::: "memory");

        // ---- compute stage S from buffer cbuf (BK=128 => 8 k16 sub-steps) ----
        const uint32_t aStage = aLane + (uint32_t)(S & 3) * (BK * 2);  // 256 B per stage
        const uint32_t bStage = sbase + OFF_YS_B + cbuf * YS_STAGE_B + bLane;

        if ((S & 3) == 0) {
            #pragma unroll
            for (int nt = 0; nt < 4; nt++)
                #pragma unroll
                for (int q = 0; q < 4; q++) acc[nt][q] = 0.0f;
        }

        #pragma unroll
        for (int ks = 0; ks < 8; ks++) {
            uint32_t a[4];
            ldsm_x4(a[0], a[1], a[2], a[3], aStage + ks * 32);
            uint32_t b0, b1, b2, b3, b4, b5, b6, b7;
            ldsm_x4(b0, b1, b2, b3, bStage + ks * 32);                     // nt 0,1
            ldsm_x4(b4, b5, b6, b7, bStage + 16 * YS_RSTRIDE_B + ks * 32); // nt 2,3
            hmma(acc[0], a, b0, b1);
            hmma(acc[1], a, b2, b3);
            hmma(acc[2], a, b4, b5);
            hmma(acc[3], a, b6, b7);
        }

        if ((S & 3) == 3) {
            const int jt = (S >> 2) * BN;
            // dump approx sims as bf16 pairs
            #pragma unroll
            for (int nt = 0; nt < 4; nt++) {
                int r0 = mw * 16 + g;
                int cw = nw * 16 + nt * 4 + t;
                __nv_bfloat162 p0 = __floats2bfloat162_rn(acc[nt][0], acc[nt][1]);
                __nv_bfloat162 p1 = __floats2bfloat162_rn(acc[nt][2], acc[nt][3]);
                simW[(r0 + 0) * SIM_WSTRIDE + cw] = *(uint32_t*)&p0;
                simW[(r0 + 8) * SIM_WSTRIDE + cw] = *(uint32_t*)&p1;
            }
            __syncthreads();

            // candidate scan: warp w owns rows 4w..4w+3
            #pragma unroll
            for (int rr = 0; rr < 4; rr++) {
                const int r = warp * 4 + rr;
                float v[4]; int jj[4];
                #pragma unroll
                for (int c = 0; c < 4; c++) {
                    v[c]  = __bfloat162float(simH[r * SIM_HSTRIDE + lane + c * 32]);
                    jj[c] = jt + lane + c * 32;
                }
                while (true) {
                    float thr = cv[(CAND - 1) * BM + r];
                    bool any = (v[0] > thr) | (v[1] > thr) | (v[2] > thr) | (v[3] > thr);
                    if (!__ballot_sync(0xffffffffu, any)) break;
                    float bmv = NEG_INF; int bj = 0x7fffffff;
                    #pragma unroll
                    for (int c = 0; c < 4; c++)
                        if (v[c] > thr && (v[c] > bmv || (v[c] == bmv && jj[c] < bj))) {
                            bmv = v[c]; bj = jj[c];
                        }
                    #pragma unroll
                    for (int off = 16; off > 0; off >>= 1) {
                        float ov = __shfl_xor_sync(0xffffffffu, bmv, off);
                        int   oj = __shfl_xor_sync(0xffffffffu, bj,  off);
                        if (ov > bmv || (ov == bmv && oj < bj)) { bmv = ov; bj = oj; }
                    }
                    if (lane == 0) {
                        int p = CAND - 1;
                        while (p > 0 && bmv > cv[(p - 1) * BM + r]) {
                            cv[p * BM + r] = cv[(p - 1) * BM + r];
                            ci[p * BM + r] = ci[(p - 1) * BM + r];
                            p--;
                        }
                        cv[p * BM + r] = bmv; ci[p * BM + r] = bj;
                    }
                    __syncwarp();
                    #pragma unroll
                    for (int c = 0; c < 4; c++)
                        if (v[c] == bmv && jj[c] == bj) v[c] = NEG_INF;
                }
            }
        }

        cbuf = (cbuf == 2) ? 0 : cbuf + 1;
        ibuf = (ibuf == 2) ? 0 : ibuf + 1;
    }
    __syncthreads();

    // ---- EXACT rescore: sequential-k fp32 fmaf chain (bit-identical to ref) ----
    {
        float acc3[3];
        int   mloc[3], cloc[3];
        const float4* xp[3];
        const float4* yp[3];
        #pragma unroll
        for (int d = 0; d < 3; d++) {
            int idx = tid + d * THREADS;        // 0..1535 = CAND*BM-1
            int m = idx / CAND, c = idx % CAND;
            mloc[d] = m; cloc[d] = c;
            xp[d] = (const float4*)(X + (size_t)(row0 + m) * KD);
            yp[d] = (const float4*)(Y + (size_t)ci[c * BM + m] * KD);
            acc3[d] = 0.0f;
        }
        for (int k4 = 0; k4 < KD / 4; k4++) {
            #pragma unroll
            for (int d = 0; d < 3; d++) {
                float4 x4 = __ldg(xp[d] + k4);
                float4 y4 = __ldg(yp[d] + k4);
                float a = acc3[d];
                a = fmaf(x4.x, y4.x, a);
                a = fmaf(x4.y, y4.y, a);
                a = fmaf(x4.z, y4.z, a);
                a = fmaf(x4.w, y4.w, a);
                acc3[d] = a;
            }
        }
        __syncthreads();   // scan reads of sim done; area becomes rv
        #pragma unroll
        for (int d = 0; d < 3; d++)
            rv[mloc[d] * CSTR + cloc[d]] = __fdiv_rn(acc3[d], 0.07f);
    }
    __syncthreads();

    // ---- exact FTZ-softmax epilogue (unchanged passing rule) ----
    if (tid < BM) {
        const int r = tid;
        float pv[CAND]; int id[CAND];
        #pragma unroll
        for (int c = 0; c < CAND; c++) { pv[c] = rv[r * CSTR + c]; id[c] = ci[c * BM + r]; }

        for (int i = 1; i < CAND; i++) {
            float kp = pv[i]; int kd = id[i];
            int j2 = i - 1;
            while (j2 >= 0 && (pv[j2] < kp || (pv[j2] == kp && id[j2] > kd))) {
                pv[j2 + 1] = pv[j2]; id[j2 + 1] = id[j2];
                j2--;
            }
            pv[j2 + 1] = kp; id[j2 + 1] = kd;
        }

        const float M = pv[0];
        float ef[CAND]; float S = 0.0f;
        #pragma unroll
        for (int c = 0; c < CAND; c++) {
            float d = pv[c] - M;
            float e = 0.0f;
            if (d > EXP_LO) {
                e = __double2float_rn(exp((double)d));
                if (e < FLT_MIN_F) e = 0.0f;
            }
            ef[c] = e;
            S += e;
        }

        int outv[TOPK]; int cnt = 0;
        for (int c = 0; c < CAND && cnt < TOPK; c++) {
            if (ef[c] > 0.0f) {
                float q = __fdiv_rn(ef[c], S);
                if (q >= FLT_MIN_F) outv[cnt++] = id[c];
            }
        }
        const int nz = cnt;
        for (int j = 0; cnt < TOPK; j++) {
            bool used = false;
            for (int q2 = 0; q2 < nz; q2++)
                if (outv[q2] == j) { used = true; break; }
            if (!used) outv[cnt++] = j;
        }

        #pragma unroll
        for (int k = 0; k < TOPK; k++)
            out[(size_t)(row0 + r) * TOPK + k] = (float)outv[k];
    }
}

extern "C" void kernel_launch(void* const* d_in, const int* in_sizes, int n_in,
                              void* d_out, int out_size)
{
    const float* X = (const float*)d_in[0];
    const float* Y = (const float*)d_in[1];
    if (n_in >= 2 && in_sizes[0] == NY * KD && in_sizes[1] == NX * KD) {
        X = (const float*)d_in[1];
        Y = (const float*)d_in[0];
    }
    float* out = (float*)d_out;
    (void)out_size;

    static int attr_set = 0;
    if (!attr_set) {
        cudaFuncSetAttribute(snf_kernel, cudaFuncAttributeMaxDynamicSharedMemorySize,
                             SMEM_BYTES);
        attr_set = 1;
    }

    const int cvt_blocks = (NX * KD / 4 + NY * KD / 4 + 255) / 256;
    cvt_kernel<<<cvt_blocks, 256>>>(X, Y);
    snf_kernel<<<NX / BM, THREADS, SMEM_BYTES>>>(X, Y, out);
}

// round 15
// speedup vs baseline: 1.7180x; 1.0075x over previous
#include <cuda_runtime.h>
#include <cuda_bf16.h>
#include <math.h>
#include <stdint.h>

#define NX 8192
#define NY 16384
#define KD 512
#define TOPK 16
#define CAND 24
#define CSTR 25

#define BM 64
#define BN 128
#define BK 128
#define THREADS 512
#define NSTAGES 512             // (NY/BN=128) * (KD/BK=4)

#define NEG_INF __int_as_float(0xff800000)
#define EXP_LO   -87.3365478515625f
#define FLT_MIN_F 1.17549435082228751e-38f

// ---- smem byte layout ----
#define OFF_XS_B   0                       // bf16 Xs [64][520]        = 66,560
#define OFF_YS_B   66560                   // bf16 Ys [3][128][136]    = 104,448
#define OFF_SIM_B  171008                  // bf16 sim [64][136]       = 17,408 (reused fp32 rv)
#define OFF_CV_B   188416                  // fp32 cv [CAND][64]       =  6,144
#define OFF_CI_B   194560                  // int  ci [CAND][64]       =  6,144
#define SMEM_BYTES 200704

#define XS_RSTRIDE_B 1040    // bytes per Xs row (520 halves)
#define YS_RSTRIDE_B 272     // bytes per Ys row (136 halves: 128 data + 8 pad)
#define YS_STAGE_B   34816   // 128 * 272
#define SIM_WSTRIDE  68
#define SIM_HSTRIDE  136

__device__ __nv_bfloat16 g_Xbf[(size_t)NX * KD];
__device__ __nv_bfloat16 g_Ybf[(size_t)NY * KD];

__global__ __launch_bounds__(256)
void cvt_kernel(const float* __restrict__ X, const float* __restrict__ Y)
{
    const size_t NXF4 = (size_t)NX * KD / 4;
    const size_t NYF4 = (size_t)NY * KD / 4;
    size_t i = (size_t)blockIdx.x * blockDim.x + threadIdx.x;
    if (i < NXF4) {
        float4 v = ((const float4*)X)[i];
        __nv_bfloat162 lo = __floats2bfloat162_rn(v.x, v.y);
        __nv_bfloat162 hi = __floats2bfloat162_rn(v.z, v.w);
        uint2 u = make_uint2(*(uint32_t*)&lo, *(uint32_t*)&hi);
        *(uint2*)&g_Xbf[i * 4] = u;
    } else if (i < NXF4 + NYF4) {
        size_t j = i - NXF4;
        float4 v = ((const float4*)Y)[j];
        __nv_bfloat162 lo = __floats2bfloat162_rn(v.x, v.y);
        __nv_bfloat162 hi = __floats2bfloat162_rn(v.z, v.w);
        uint2 u = make_uint2(*(uint32_t*)&lo, *(uint32_t*)&hi);
        *(uint2*)&g_Ybf[j * 4] = u;
    }
}

__device__ __forceinline__ uint32_t smem_u32(const void* p) {
    uint32_t a;
    asm("{ .reg .u64 t; cvta.to.shared.u64 t, %1; cvt.u32.u64 %0, t; }" : "=r"(a) : "l"(p));
    return a;
}
__device__ __forceinline__ void cp16(uint32_t dst, const void* src) {
    asm volatile("cp.async.cg.shared.global [%0], [%1], 16;\n" :: "r"(dst), "l"(src) : "memory");
}
__device__ __forceinline__ void ldsm_x4(uint32_t& r0, uint32_t& r1, uint32_t& r2, uint32_t& r3,
                                        uint32_t addr)
{
    asm volatile("ldmatrix.sync.aligned.m8n8.x4.shared.b16 {%0,%1,%2,%3}, [%4];"
                 : "=r"(r0), "=r"(r1), "=r"(r2), "=r"(r3) : "r"(addr));
}
__device__ __forceinline__ void hmma(float c[4], const uint32_t a[4],
                                     uint32_t b0, uint32_t b1)
{
    asm volatile(
        "mma.sync.aligned.m16n8k16.row.col.f32.bf16.bf16.f32 "
        "{%0,%1,%2,%3}, {%4,%5,%6,%7}, {%8,%9}, {%0,%1,%2,%3};"
        : "+f"(c[0]), "+f"(c[1]), "+f"(c[2]), "+f"(c[3])
        : "r"(a[0]), "r"(a[1]), "r"(a[2]), "r"(a[3]), "r"(b0), "r"(b1));
}

__global__ __launch_bounds__(THREADS, 1)
void snf_kernel(const float* __restrict__ X, const float* __restrict__ Y,
                float* __restrict__ out)
{
    extern __shared__ __align__(16) char smem[];
    uint32_t*       simW = (uint32_t*)(smem + OFF_SIM_B);
    __nv_bfloat16*  simH = (__nv_bfloat16*)(smem + OFF_SIM_B);
    float*          rv   = (float*)(smem + OFF_SIM_B);
    float*          cv   = (float*)(smem + OFF_CV_B);
    int*            ci   = (int*)(smem + OFF_CI_B);

    const int tid  = threadIdx.x;
    const int warp = tid >> 5;
    const int lane = tid & 31;
    const int g    = lane >> 2;
    const int t    = lane & 3;
    const int mw   = warp & 3;     // m group (16 rows)
    const int nw   = warp >> 2;    // n group (32 cols)
    const int row0 = blockIdx.x * BM;
    const uint32_t sbase = smem_u32(smem);

    // hoisted LDSM lane addresses
    const uint32_t aLane = sbase + OFF_XS_B
        + (uint32_t)(mw * 16 + (lane & 15)) * XS_RSTRIDE_B + ((lane >> 4) << 4);
    const uint32_t bLane = (uint32_t)(nw * 32 + ((lane >> 4) & 1) * 8 + (lane & 7)) * YS_RSTRIDE_B
        + (((lane >> 3) & 1) << 4);

    // ---- prologue: issue cp.async stages 0,1 ----
    #pragma unroll
    for (int ps = 0; ps < 2; ps++) {
        int kt1 = ps * BK;            // jt=0 for ps<4
        #pragma unroll
        for (int s2 = 0; s2 < 4; s2++) {
            int ch = tid + s2 * THREADS;   // 0..2047
            int n = ch >> 4, c = ch & 15;
            cp16(sbase + OFF_YS_B + ps * YS_STAGE_B + n * YS_RSTRIDE_B + c * 16,
                 g_Ybf + (size_t)n * KD + kt1 + c * 8);
        }
        asm volatile("cp.async.commit_group;" ::: "memory");
    }

    // ---- fill bf16 Xs tile ----
    {
        const uint4* xsrc = (const uint4*)(g_Xbf + (size_t)row0 * KD);
        #pragma unroll
        for (int i = 0; i < 8; i++) {
            int f = tid + i * THREADS;   // 0..4095
            int m = f >> 6, c = f & 63;
            *(uint4*)(smem + OFF_XS_B + m * XS_RSTRIDE_B + c * 16) = xsrc[m * 64 + c];
        }
    }
    for (int i = tid; i < CAND * BM; i += THREADS) { cv[i] = NEG_INF; ci[i] = 0; }

    float acc[4][4];   // [nt][quad] = 16 regs
    int cbuf = 0, ibuf = 2;

    for (int S = 0; S < NSTAGES; S++) {
        asm volatile("cp.async.wait_group 1;" ::: "memory");
        __syncthreads();

        // issue stage S+2 into buffer ibuf (old contents consumed at stage S-1)
        if (S + 2 < NSTAGES) {
            int ps = S + 2;
            int jt1 = ps >> 2, kt1 = (ps & 3) * BK;
            uint32_t dstb = sbase + OFF_YS_B + ibuf * YS_STAGE_B;
            const __nv_bfloat16* srcb = g_Ybf + (size_t)jt1 * BN * KD + kt1;
            #pragma unroll
            for (int s2 = 0; s2 < 4; s2++) {
                int ch = tid + s2 * THREADS;
                int n = ch >> 4, c = ch & 15;
                cp16(dstb + n * YS_RSTRIDE_B + c * 16, srcb + (size_t)n * KD + c * 8);
            }
        }
        asm volatile("cp.async.commit_group;" ::: "memory");

        // ---- compute stage S from buffer cbuf (BK=128 => 8 k16 sub-steps),
        //      fragments double-buffered: LDSM for ks+1 issued before HMMAs of ks ----
        const uint32_t aStage = aLane + (uint32_t)(S & 3) * (BK * 2);  // 256 B per stage
        const uint32_t bStage = sbase + OFF_YS_B + cbuf * YS_STAGE_B + bLane;

        if ((S & 3) == 0) {
            #pragma unroll
            for (int nt = 0; nt < 4; nt++)
                #pragma unroll
                for (int q = 0; q < 4; q++) acc[nt][q] = 0.0f;
        }

        {
            uint32_t af[2][4], bb[2][8];
            ldsm_x4(af[0][0], af[0][1], af[0][2], af[0][3], aStage);
            ldsm_x4(bb[0][0], bb[0][1], bb[0][2], bb[0][3], bStage);
            ldsm_x4(bb[0][4], bb[0][5], bb[0][6], bb[0][7], bStage + 16 * YS_RSTRIDE_B);
            #pragma unroll
            for (int ks = 0; ks < 8; ks++) {
                const int cur = ks & 1, nxt = cur ^ 1;
                if (ks < 7) {
                    ldsm_x4(af[nxt][0], af[nxt][1], af[nxt][2], af[nxt][3],
                            aStage + (ks + 1) * 32);
                    ldsm_x4(bb[nxt][0], bb[nxt][1], bb[nxt][2], bb[nxt][3],
                            bStage + (ks + 1) * 32);
                    ldsm_x4(bb[nxt][4], bb[nxt][5], bb[nxt][6], bb[nxt][7],
                            bStage + 16 * YS_RSTRIDE_B + (ks + 1) * 32);
                }
                hmma(acc[0], af[cur], bb[cur][0], bb[cur][1]);
                hmma(acc[1], af[cur], bb[cur][2], bb[cur][3]);
                hmma(acc[2], af[cur], bb[cur][4], bb[cur][5]);
                hmma(acc[3], af[cur], bb[cur][6], bb[cur][7]);
            }
        }

        if ((S & 3) == 3) {
            const int jt = (S >> 2) * BN;
            // dump approx sims as bf16 pairs
            #pragma unroll
            for (int nt = 0; nt < 4; nt++) {
                int r0 = mw * 16 + g;
                int cw = nw * 16 + nt * 4 + t;
                __nv_bfloat162 p0 = __floats2bfloat162_rn(acc[nt][0], acc[nt][1]);
                __nv_bfloat162 p1 = __floats2bfloat162_rn(acc[nt][2], acc[nt][3]);
                simW[(r0 + 0) * SIM_WSTRIDE + cw] = *(uint32_t*)&p0;
                simW[(r0 + 8) * SIM_WSTRIDE + cw] = *(uint32_t*)&p1;
            }
            __syncthreads();

            // candidate scan: warp w owns rows 4w..4w+3
            #pragma unroll
            for (int rr = 0; rr < 4; rr++) {
                const int r = warp * 4 + rr;
                float v[4]; int jj[4];
                #pragma unroll
                for (int c = 0; c < 4; c++) {
                    v[c]  = __bfloat162float(simH[r * SIM_HSTRIDE + lane + c * 32]);
                    jj[c] = jt + lane + c * 32;
                }
                while (true) {
                    float thr = cv[(CAND - 1) * BM + r];
                    bool any = (v[0] > thr) | (v[1] > thr) | (v[2] > thr) | (v[3] > thr);
                    if (!__ballot_sync(0xffffffffu, any)) break;
                    float bmv = NEG_INF; int bj = 0x7fffffff;
                    #pragma unroll
                    for (int c = 0; c < 4; c++)
                        if (v[c] > thr && (v[c] > bmv || (v[c] == bmv && jj[c] < bj))) {
                            bmv = v[c]; bj = jj[c];
                        }
                    #pragma unroll
                    for (int off = 16; off > 0; off >>= 1) {
                        float ov = __shfl_xor_sync(0xffffffffu, bmv, off);
                        int   oj = __shfl_xor_sync(0xffffffffu, bj,  off);
                        if (ov > bmv || (ov == bmv && oj < bj)) { bmv = ov; bj = oj; }
                    }
                    if (lane == 0) {
                        int p = CAND - 1;
                        while (p > 0 && bmv > cv[(p - 1) * BM + r]) {
                            cv[p * BM + r] = cv[(p - 1) * BM + r];
                            ci[p * BM + r] = ci[(p - 1) * BM + r];
                            p--;
                        }
                        cv[p * BM + r] = bmv; ci[p * BM + r] = bj;
                    }
                    __syncwarp();
                    #pragma unroll
                    for (int c = 0; c < 4; c++)
                        if (v[c] == bmv && jj[c] == bj) v[c] = NEG_INF;
                }
            }
        }

        cbuf = (cbuf == 2) ? 0 : cbuf + 1;
        ibuf = (ibuf == 2) ? 0 : ibuf + 1;
    }
    __syncthreads();

    // ---- EXACT rescore: sequential-k fp32 fmaf chain (bit-identical to ref) ----
    {
        float acc3[3];
        int   mloc[3], cloc[3];
        const float4* xp[3];
        const float4* yp[3];
        #pragma unroll
        for (int d = 0; d < 3; d++) {
            int idx = tid + d * THREADS;        // 0..1535 = CAND*BM-1
            int m = idx / CAND, c = idx % CAND;
            mloc[d] = m; cloc[d] = c;
            xp[d] = (const float4*)(X + (size_t)(row0 + m) * KD);
            yp[d] = (const float4*)(Y + (size_t)ci[c * BM + m] * KD);
            acc3[d] = 0.0f;
        }
        for (int k4 = 0; k4 < KD / 4; k4++) {
            #pragma unroll
            for (int d = 0; d < 3; d++) {
                float4 x4 = __ldg(xp[d] + k4);
                float4 y4 = __ldg(yp[d] + k4);
                float a = acc3[d];
                a = fmaf(x4.x, y4.x, a);
                a = fmaf(x4.y, y4.y, a);
                a = fmaf(x4.z, y4.z, a);
                a = fmaf(x4.w, y4.w, a);
                acc3[d] = a;
            }
        }
        __syncthreads();   // scan reads of sim done; area becomes rv
        #pragma unroll
        for (int d = 0; d < 3; d++)
            rv[mloc[d] * CSTR + cloc[d]] = __fdiv_rn(acc3[d], 0.07f);
    }
    __syncthreads();

    // ---- exact FTZ-softmax epilogue (unchanged passing rule) ----
    if (tid < BM) {
        const int r = tid;
        float pv[CAND]; int id[CAND];
        #pragma unroll
        for (int c = 0; c < CAND; c++) { pv[c] = rv[r * CSTR + c]; id[c] = ci[c * BM + r]; }

        for (int i = 1; i < CAND; i++) {
            float kp = pv[i]; int kd = id[i];
            int j2 = i - 1;
            while (j2 >= 0 && (pv[j2] < kp || (pv[j2] == kp && id[j2] > kd))) {
                pv[j2 + 1] = pv[j2]; id[j2 + 1] = id[j2];
                j2--;
            }
            pv[j2 + 1] = kp; id[j2 + 1] = kd;
        }

        const float M = pv[0];
        float ef[CAND]; float S = 0.0f;
        #pragma unroll
        for (int c = 0; c < CAND; c++) {
            float d = pv[c] - M;
            float e = 0.0f;
            if (d > EXP_LO) {
                e = __double2float_rn(exp((double)d));
                if (e < FLT_MIN_F) e = 0.0f;
            }
            ef[c] = e;
            S += e;
        }

        int outv[TOPK]; int cnt = 0;
        for (int c = 0; c < CAND && cnt < TOPK; c++) {
            if (ef[c] > 0.0f) {
                float q = __fdiv_rn(ef[c], S);
                if (q >= FLT_MIN_F) outv[cnt++] = id[c];
            }
        }
        const int nz = cnt;
        for (int j = 0; cnt < TOPK; j++) {
            bool used = false;
            for (int q2 = 0; q2 < nz; q2++)
                if (outv[q2] == j) { used = true; break; }
            if (!used) outv[cnt++] = j;
        }

        #pragma unroll
        for (int k = 0; k < TOPK; k++)
            out[(size_t)(row0 + r) * TOPK + k] = (float)outv[k];
    }
}

extern "C" void kernel_launch(void* const* d_in, const int* in_sizes, int n_in,
                              void* d_out, int out_size)
{
    const float* X = (const float*)d_in[0];
    const float* Y = (const float*)d_in[1];
    if (n_in >= 2 && in_sizes[0] == NY * KD && in_sizes[1] == NX * KD) {
        X = (const float*)d_in[1];
        Y = (const float*)d_in[0];
    }
    float* out = (float*)d_out;
    (void)out_size;

    static int attr_set = 0;
    if (!attr_set) {
        cudaFuncSetAttribute(snf_kernel, cudaFuncAttributeMaxDynamicSharedMemorySize,
                             SMEM_BYTES);
        attr_set = 1;
    }

    const int cvt_blocks = (NX * KD / 4 + NY * KD / 4 + 255) / 256;
    cvt_kernel<<<cvt_blocks, 256>>>(X, Y);
    snf_kernel<<<NX / BM, THREADS, SMEM_BYTES>>>(X, Y, out);
}

// round 16
// speedup vs baseline: 2.0341x; 1.1840x over previous
#include <cuda_runtime.h>
#include <cuda_bf16.h>
#include <math.h>
#include <stdint.h>

#define NX 8192
#define NY 16384
#define KD 512
#define TOPK 16
#define CAND 24
#define CSTR 25

#define BM 64
#define BN 128
#define BK 256                  // fp8 elems per stage
#define THREADS 512
#define NSTAGES 256             // (NY/BN=128) * (KD/BK=2)

#define NEG_INF __int_as_float(0xff800000)
#define EXP_LO   -87.3365478515625f
#define FLT_MIN_F 1.17549435082228751e-38f

// ---- smem byte layout ----
#define OFF_XS_B   0                       // fp8 Xs [64][528]         = 33,792
#define OFF_YS_B   33792                   // fp8 Ys [3][128][272]     = 104,448
#define OFF_SIM_B  138240                  // bf16 sim [64][136]       = 17,408 (reused fp32 rv)
#define OFF_CV_B   155648                  // fp32 cv [CAND][64]       =  6,144
#define OFF_CI_B   161792                  // int  ci [CAND][64]       =  6,144
#define SMEM_BYTES 167936

#define XS_RSTRIDE_B 528     // bytes per Xs row (512 data + 16 pad); 132 w % 32 = 4 -> ldsm ok
#define YS_RSTRIDE_B 272     // bytes per Ys row (256 data + 16 pad); 68 w % 32 = 4 -> ldsm ok
#define YS_STAGE_B   34816   // 128 * 272
#define SIM_WSTRIDE  68
#define SIM_HSTRIDE  136

__device__ uint8_t g_Xf8[(size_t)NX * KD];
__device__ uint8_t g_Yf8[(size_t)NY * KD];

// fp32 x8 -> e4m3 x8 (packed), byte i = elem i
__device__ __forceinline__ uint32_t pack_e4m3x4(float f0, float f1, float f2, float f3)
{
    uint32_t d;
    asm("{\n\t.reg .b16 lo, hi;\n\t"
        "cvt.rn.satfinite.e4m3x2.f32 lo, %2, %1;\n\t"
        "cvt.rn.satfinite.e4m3x2.f32 hi, %4, %3;\n\t"
        "mov.b32 %0, {lo, hi};\n\t}"
        : "=r"(d) : "f"(f0), "f"(f1), "f"(f2), "f"(f3));
    return d;
}

__global__ __launch_bounds__(256)
void cvt_kernel(const float* __restrict__ X, const float* __restrict__ Y)
{
    const size_t NX8 = (size_t)NX * KD / 8;   // 524,288
    const size_t NY8 = (size_t)NY * KD / 8;   // 1,048,576
    size_t i = (size_t)blockIdx.x * blockDim.x + threadIdx.x;
    if (i < NX8) {
        float4 a = ((const float4*)X)[i * 2];
        float4 b = ((const float4*)X)[i * 2 + 1];
        uint2 u = make_uint2(pack_e4m3x4(a.x, a.y, a.z, a.w),
                             pack_e4m3x4(b.x, b.y, b.z, b.w));
        *(uint2*)&g_Xf8[i * 8] = u;
    } else if (i < NX8 + NY8) {
        size_t j = i - NX8;
        float4 a = ((const float4*)Y)[j * 2];
        float4 b = ((const float4*)Y)[j * 2 + 1];
        uint2 u = make_uint2(pack_e4m3x4(a.x, a.y, a.z, a.w),
                             pack_e4m3x4(b.x, b.y, b.z, b.w));
        *(uint2*)&g_Yf8[j * 8] = u;
    }
}

__device__ __forceinline__ uint32_t smem_u32(const void* p) {
    uint32_t a;
    asm("{ .reg .u64 t; cvta.to.shared.u64 t, %1; cvt.u32.u64 %0, t; }" : "=r"(a) : "l"(p));
    return a;
}
__device__ __forceinline__ void cp16(uint32_t dst, const void* src) {
    asm volatile("cp.async.cg.shared.global [%0], [%1], 16;\n" :: "r"(dst), "l"(src) : "memory");
}
__device__ __forceinline__ void ldsm_x4(uint32_t& r0, uint32_t& r1, uint32_t& r2, uint32_t& r3,
                                        uint32_t addr)
{
    asm volatile("ldmatrix.sync.aligned.m8n8.x4.shared.b16 {%0,%1,%2,%3}, [%4];"
                 : "=r"(r0), "=r"(r1), "=r"(r2), "=r"(r3) : "r"(addr));
}
__device__ __forceinline__ void qmma(float c[4], const uint32_t a[4],
                                     uint32_t b0, uint32_t b1)
{
    asm volatile(
        "mma.sync.aligned.m16n8k32.row.col.f32.e4m3.e4m3.f32 "
        "{%0,%1,%2,%3}, {%4,%5,%6,%7}, {%8,%9}, {%0,%1,%2,%3};"
        : "+f"(c[0]), "+f"(c[1]), "+f"(c[2]), "+f"(c[3])
        : "r"(a[0]), "r"(a[1]), "r"(a[2]), "r"(a[3]), "r"(b0), "r"(b1));
}

__global__ __launch_bounds__(THREADS, 1)
void snf_kernel(const float* __restrict__ X, const float* __restrict__ Y,
                float* __restrict__ out)
{
    extern __shared__ __align__(16) char smem[];
    uint32_t*       simW = (uint32_t*)(smem + OFF_SIM_B);
    __nv_bfloat16*  simH = (__nv_bfloat16*)(smem + OFF_SIM_B);
    float*          rv   = (float*)(smem + OFF_SIM_B);
    float*          cv   = (float*)(smem + OFF_CV_B);
    int*            ci   = (int*)(smem + OFF_CI_B);

    const int tid  = threadIdx.x;
    const int warp = tid >> 5;
    const int lane = tid & 31;
    const int g    = lane >> 2;
    const int t    = lane & 3;
    const int mw   = warp & 3;     // m group (16 rows)
    const int nw   = warp >> 2;    // n group (32 cols)
    const int row0 = blockIdx.x * BM;
    const uint32_t sbase = smem_u32(smem);

    // hoisted LDSM lane addresses (16-byte k-chunks of fp8 rows)
    // A x4: lanes 0-15 rows m0..15 chunk0, lanes 16-31 same rows chunk1 (+16B)
    const uint32_t aLane = sbase + OFF_XS_B
        + (uint32_t)(mw * 16 + (lane & 15)) * XS_RSTRIDE_B + ((lane >> 4) << 4);
    // B x4: two n8 tiles x two 16B k-chunks
    const uint32_t bLane = (uint32_t)(nw * 32 + ((lane >> 4) & 1) * 8 + (lane & 7)) * YS_RSTRIDE_B
        + (((lane >> 3) & 1) << 4);

    // ---- prologue: issue cp.async stages 0,1 ----
    #pragma unroll
    for (int ps = 0; ps < 2; ps++) {
        int kt1 = ps * BK;            // jt=0 for ps<2
        #pragma unroll
        for (int s2 = 0; s2 < 4; s2++) {
            int ch = tid + s2 * THREADS;   // 0..2047
            int n = ch >> 4, c = ch & 15;
            cp16(sbase + OFF_YS_B + ps * YS_STAGE_B + n * YS_RSTRIDE_B + c * 16,
                 g_Yf8 + (size_t)n * KD + kt1 + c * 16);
        }
        asm volatile("cp.async.commit_group;" ::: "memory");
    }

    // ---- fill fp8 Xs tile (64 x 512 B) ----
    {
        const uint4* xsrc = (const uint4*)(g_Xf8 + (size_t)row0 * KD);
        #pragma unroll
        for (int i = 0; i < 4; i++) {
            int f = tid + i * THREADS;   // 0..2047
            int m = f >> 5, c = f & 31;
            *(uint4*)(smem + OFF_XS_B + m * XS_RSTRIDE_B + c * 16) = xsrc[m * 32 + c];
        }
    }
    for (int i = tid; i < CAND * BM; i += THREADS) { cv[i] = NEG_INF; ci[i] = 0; }

    float acc[4][4];   // [nt][quad] = 16 regs
    int cbuf = 0, ibuf = 2;

    for (int S = 0; S < NSTAGES; S++) {
        asm volatile("cp.async.wait_group 1;" ::: "memory");
        __syncthreads();

        // issue stage S+2 into buffer ibuf (old contents consumed at stage S-1)
        if (S + 2 < NSTAGES) {
            int ps = S + 2;
            int jt1 = ps >> 1, kt1 = (ps & 1) * BK;
            uint32_t dstb = sbase + OFF_YS_B + ibuf * YS_STAGE_B;
            const uint8_t* srcb = g_Yf8 + (size_t)jt1 * BN * KD + kt1;
            #pragma unroll
            for (int s2 = 0; s2 < 4; s2++) {
                int ch = tid + s2 * THREADS;
                int n = ch >> 4, c = ch & 15;
                cp16(dstb + n * YS_RSTRIDE_B + c * 16, srcb + (size_t)n * KD + c * 16);
            }
        }
        asm volatile("cp.async.commit_group;" ::: "memory");

        // ---- compute stage S from buffer cbuf (BK=256 fp8 => 8 k32 sub-steps) ----
        const uint32_t aStage = aLane + (uint32_t)(S & 1) * BK;   // 256 B per stage
        const uint32_t bStage = sbase + OFF_YS_B + cbuf * YS_STAGE_B + bLane;

        if ((S & 1) == 0) {
            #pragma unroll
            for (int nt = 0; nt < 4; nt++)
                #pragma unroll
                for (int q = 0; q < 4; q++) acc[nt][q] = 0.0f;
        }

        #pragma unroll
        for (int ks = 0; ks < 8; ks++) {
            uint32_t a[4];
            ldsm_x4(a[0], a[1], a[2], a[3], aStage + ks * 32);
            uint32_t b0, b1, b2, b3, b4, b5, b6, b7;
            ldsm_x4(b0, b1, b2, b3, bStage + ks * 32);                     // nt 0,1
            ldsm_x4(b4, b5, b6, b7, bStage + 16 * YS_RSTRIDE_B + ks * 32); // nt 2,3
            qmma(acc[0], a, b0, b1);
            qmma(acc[1], a, b2, b3);
            qmma(acc[2], a, b4, b5);
            qmma(acc[3], a, b6, b7);
        }

        if ((S & 1) == 1) {
            const int jt = (S >> 1) * BN;
            // dump approx sims as bf16 pairs
            #pragma unroll
            for (int nt = 0; nt < 4; nt++) {
                int r0 = mw * 16 + g;
                int cw = nw * 16 + nt * 4 + t;
                __nv_bfloat162 p0 = __floats2bfloat162_rn(acc[nt][0], acc[nt][1]);
                __nv_bfloat162 p1 = __floats2bfloat162_rn(acc[nt][2], acc[nt][3]);
                simW[(r0 + 0) * SIM_WSTRIDE + cw] = *(uint32_t*)&p0;
                simW[(r0 + 8) * SIM_WSTRIDE + cw] = *(uint32_t*)&p1;
            }
            __syncthreads();

            // candidate scan: warp w owns rows 4w..4w+3
            #pragma unroll
            for (int rr = 0; rr < 4; rr++) {
                const int r = warp * 4 + rr;
                float v[4]; int jj[4];
                #pragma unroll
                for (int c = 0; c < 4; c++) {
                    v[c]  = __bfloat162float(simH[r * SIM_HSTRIDE + lane + c * 32]);
                    jj[c] = jt + lane + c * 32;
                }
                while (true) {
                    float thr = cv[(CAND - 1) * BM + r];
                    bool any = (v[0] > thr) | (v[1] > thr) | (v[2] > thr) | (v[3] > thr);
                    if (!__ballot_sync(0xffffffffu, any)) break;
                    float bmv = NEG_INF; int bj = 0x7fffffff;
                    #pragma unroll
                    for (int c = 0; c < 4; c++)
                        if (v[c] > thr && (v[c] > bmv || (v[c] == bmv && jj[c] < bj))) {
                            bmv = v[c]; bj = jj[c];
                        }
                    #pragma unroll
                    for (int off = 16; off > 0; off >>= 1) {
                        float ov = __shfl_xor_sync(0xffffffffu, bmv, off);
                        int   oj = __shfl_xor_sync(0xffffffffu, bj,  off);
                        if (ov > bmv || (ov == bmv && oj < bj)) { bmv = ov; bj = oj; }
                    }
                    if (lane == 0) {
                        int p = CAND - 1;
                        while (p > 0 && bmv > cv[(p - 1) * BM + r]) {
                            cv[p * BM + r] = cv[(p - 1) * BM + r];
                            ci[p * BM + r] = ci[(p - 1) * BM + r];
                            p--;
                        }
                        cv[p * BM + r] = bmv; ci[p * BM + r] = bj;
                    }
                    __syncwarp();
                    #pragma unroll
                    for (int c = 0; c < 4; c++)
                        if (v[c] == bmv && jj[c] == bj) v[c] = NEG_INF;
                }
            }
        }

        cbuf = (cbuf == 2) ? 0 : cbuf + 1;
        ibuf = (ibuf == 2) ? 0 : ibuf + 1;
    }
    __syncthreads();

    // ---- EXACT rescore: sequential-k fp32 fmaf chain (bit-identical to ref) ----
    {
        float acc3[3];
        int   mloc[3], cloc[3];
        const float4* xp[3];
        const float4* yp[3];
        #pragma unroll
        for (int d = 0; d < 3; d++) {
            int idx = tid + d * THREADS;        // 0..1535 = CAND*BM-1
            int m = idx / CAND, c = idx % CAND;
            mloc[d] = m; cloc[d] = c;
            xp[d] = (const float4*)(X + (size_t)(row0 + m) * KD);
            yp[d] = (const float4*)(Y + (size_t)ci[c * BM + m] * KD);
            acc3[d] = 0.0f;
        }
        for (int k4 = 0; k4 < KD / 4; k4++) {
            #pragma unroll
            for (int d = 0; d < 3; d++) {
                float4 x4 = __ldg(xp[d] + k4);
                float4 y4 = __ldg(yp[d] + k4);
                float a = acc3[d];
                a = fmaf(x4.x, y4.x, a);
                a = fmaf(x4.y, y4.y, a);
                a = fmaf(x4.z, y4.z, a);
                a = fmaf(x4.w, y4.w, a);
                acc3[d] = a;
            }
        }
        __syncthreads();   // scan reads of sim done; area becomes rv
        #pragma unroll
        for (int d = 0; d < 3; d++)
            rv[mloc[d] * CSTR + cloc[d]] = __fdiv_rn(acc3[d], 0.07f);
    }
    __syncthreads();

    // ---- exact FTZ-softmax epilogue (unchanged passing rule) ----
    if (tid < BM) {
        const int r = tid;
        float pv[CAND]; int id[CAND];
        #pragma unroll
        for (int c = 0; c < CAND; c++) { pv[c] = rv[r * CSTR + c]; id[c] = ci[c * BM + r]; }

        for (int i = 1; i < CAND; i++) {
            float kp = pv[i]; int kd = id[i];
            int j2 = i - 1;
            while (j2 >= 0 && (pv[j2] < kp || (pv[j2] == kp && id[j2] > kd))) {
                pv[j2 + 1] = pv[j2]; id[j2 + 1] = id[j2];
                j2--;
            }
            pv[j2 + 1] = kp; id[j2 + 1] = kd;
        }

        const float M = pv[0];
        float ef[CAND]; float S = 0.0f;
        #pragma unroll
        for (int c = 0; c < CAND; c++) {
            float d = pv[c] - M;
            float e = 0.0f;
            if (d > EXP_LO) {
                e = __double2float_rn(exp((double)d));
                if (e < FLT_MIN_F) e = 0.0f;
            }
            ef[c] = e;
            S += e;
        }

        int outv[TOPK]; int cnt = 0;
        for (int c = 0; c < CAND && cnt < TOPK; c++) {
            if (ef[c] > 0.0f) {
                float q = __fdiv_rn(ef[c], S);
                if (q >= FLT_MIN_F) outv[cnt++] = id[c];
            }
        }
        const int nz = cnt;
        for (int j = 0; cnt < TOPK; j++) {
            bool used = false;
            for (int q2 = 0; q2 < nz; q2++)
                if (outv[q2] == j) { used = true; break; }
            if (!used) outv[cnt++] = j;
        }

        #pragma unroll
        for (int k = 0; k < TOPK; k++)
            out[(size_t)(row0 + r) * TOPK + k] = (float)outv[k];
    }
}

extern "C" void kernel_launch(void* const* d_in, const int* in_sizes, int n_in,
                              void* d_out, int out_size)
{
    const float* X = (const float*)d_in[0];
    const float* Y = (const float*)d_in[1];
    if (n_in >= 2 && in_sizes[0] == NY * KD && in_sizes[1] == NX * KD) {
        X = (const float*)d_in[1];
        Y = (const float*)d_in[0];
    }
    float* out = (float*)d_out;
    (void)out_size;

    static int attr_set = 0;
    if (!attr_set) {
        cudaFuncSetAttribute(snf_kernel, cudaFuncAttributeMaxDynamicSharedMemorySize,
                             SMEM_BYTES);
        attr_set = 1;
    }

    const int cvt_blocks = (int)(((size_t)NX * KD / 8 + (size_t)NY * KD / 8 + 255) / 256);
    cvt_kernel<<<cvt_blocks, 256>>>(X, Y);
    snf_kernel<<<NX / BM, THREADS, SMEM_BYTES>>>(X, Y, out);
}